// round 1
// baseline (speedup 1.0000x reference)
#include <cuda_runtime.h>
#include <cstdint>
#include <math.h>

#define BB 64
#define LL 200
#define DD 128
#define MM 50
#define NQ 10000
#define NTOK (BB*LL)

// ---------------- device scratch (no allocations allowed) ----------------
__device__ float g_w[NTOK*MM];        // softmax weights  [tok][50]
__device__ float g_e[NTOK*DD];        // erase gate       [tok][128]
__device__ float g_a[NTOK*DD];        // add gate         [tok][128]
__device__ float g_read[NTOK*DD];     // read vectors     [tok][128]
__device__ float g_eWT[DD*DD];        // e_W transposed [k][d]
__device__ float g_aWT[DD*DD];
__device__ float g_fWT[2*DD*DD];      // f_W transposed [k(256)][d(128)]

// ---------------- f32x2 helpers (sm_10x packed fp32 pipe) ----------------
__device__ __forceinline__ unsigned long long splat2(float x){
    unsigned long long r; asm("mov.b64 %0, {%1, %1};" : "=l"(r) : "f"(x)); return r;
}
__device__ __forceinline__ void fma2(unsigned long long &d, unsigned long long a, unsigned long long b){
    asm("fma.rn.f32x2 %0, %1, %2, %0;" : "+l"(d) : "l"(a), "l"(b));
}
__device__ __forceinline__ float2 unpk(unsigned long long v){
    float2 r; asm("mov.b64 {%0, %1}, %2;" : "=f"(r.x), "=f"(r.y) : "l"(v)); return r;
}
__device__ __forceinline__ float sigmoidf_(float x){ return 1.f/(1.f + __expf(-x)); }

// ---------------- kernel 0: one-time weight transposes --------------------
__global__ void tr_kernel(const float* __restrict__ eW, const float* __restrict__ aW,
                          const float* __restrict__ fW){
    int i = blockIdx.x*256 + threadIdx.x;
    if (i < DD*DD){
        int d = i >> 7, k = i & 127;
        g_eWT[k*DD + d] = eW[i];
        g_aWT[k*DD + d] = aW[i];
    }
    if (i < 2*DD*DD){
        int d = i >> 8, k = i & 255;      // fW is [128][256]
        g_fWT[k*DD + d] = fW[i];
    }
}

// ---------------- kernel 1: attention weights w = softmax(k @ Mk^T) -------
// 128 threads, 8 tokens/block, 16 lanes per token (in-warp groups).
#define W_TOK 8
__global__ void __launch_bounds__(128) w_kernel(const int* __restrict__ q,
                                                const float* __restrict__ k_emb,
                                                const float* __restrict__ Mk){
    __shared__ float sMk[64*132];   // padded pitch 132 -> conflict-light reads
    __shared__ float sK[W_TOK*DD];
    const int tid = threadIdx.x;
    const int tokbase = blockIdx.x * W_TOK;

    for (int i = tid; i < 64*132; i += 128) sMk[i] = 0.f;
    __syncthreads();
    for (int i = tid; i < MM*DD; i += 128) sMk[(i>>7)*132 + (i&127)] = Mk[i];
    #pragma unroll
    for (int jj = 0; jj < W_TOK; jj++)
        sK[jj*DD + tid] = k_emb[(size_t)q[tokbase+jj]*DD + tid];
    __syncthreads();

    const int j = tid >> 4, l16 = tid & 15;
    const float* kj = sK + j*DD;
    float acc[4] = {0.f,0.f,0.f,0.f};
    #pragma unroll 4
    for (int dd = 0; dd < DD; dd += 4){
        float4 kv = *(const float4*)(kj + dd);
        #pragma unroll
        for (int i = 0; i < 4; i++){
            int m = l16 + 16*i;
            float4 mk = *(const float4*)(sMk + m*132 + dd);
            acc[i] += kv.x*mk.x + kv.y*mk.y + kv.z*mk.z + kv.w*mk.w;
        }
    }
    #pragma unroll
    for (int i = 0; i < 4; i++) if (l16 + 16*i >= MM) acc[i] = -1e30f;
    float mx = fmaxf(fmaxf(acc[0],acc[1]), fmaxf(acc[2],acc[3]));
    #pragma unroll
    for (int o = 8; o >= 1; o >>= 1) mx = fmaxf(mx, __shfl_xor_sync(0xffffffffu, mx, o));
    float ex[4], s = 0.f;
    #pragma unroll
    for (int i = 0; i < 4; i++){ ex[i] = __expf(acc[i] - mx); s += ex[i]; }
    #pragma unroll
    for (int o = 8; o >= 1; o >>= 1) s += __shfl_xor_sync(0xffffffffu, s, o);
    float inv = 1.f / s;
    #pragma unroll
    for (int i = 0; i < 4; i++){
        int m = l16 + 16*i;
        if (m < MM) g_w[(size_t)(tokbase + j)*MM + m] = ex[i]*inv;
    }
}

// ---------------- kernel 2: e = sigmoid(v@eW^T+b), a = tanh(v@aW^T+b) -----
// 256 threads, 64 tokens/block. Micro-tile: 8 tokens (4 f32x2 pairs) x 4 dims.
#define EA_TOK 64
#define VP 68
#define EA_SMEM ((2*DD*DD + DD*VP)*4)
__global__ void __launch_bounds__(256) ea_kernel(const int* __restrict__ q,
                                                 const int* __restrict__ r,
                                                 const float* __restrict__ v_emb,
                                                 const float* __restrict__ e_b,
                                                 const float* __restrict__ a_b){
    extern __shared__ float sm[];
    float* sE = sm;
    float* sA = sm + DD*DD;
    float* sV = sm + 2*DD*DD;   // [kk=128][VP], tokens contiguous
    const int tid = threadIdx.x, lane = tid & 31, wp = tid >> 5;
    const int tokbase = blockIdx.x * EA_TOK;

    for (int i = tid; i < DD*DD; i += 256){ sE[i] = g_eWT[i]; sA[i] = g_aWT[i]; }
    for (int jj = wp; jj < EA_TOK; jj += 8){
        int tok = tokbase + jj;
        int x = q[tok] + NQ * r[tok];
        const float* vr = v_emb + (size_t)x * DD;
        #pragma unroll
        for (int dd = lane; dd < DD; dd += 32) sV[dd*VP + jj] = vr[dd];
    }
    __syncthreads();

    unsigned long long aE[4][4], aA[4][4];
    #pragma unroll
    for (int j=0;j<4;j++)
        #pragma unroll
        for (int p=0;p<4;p++){ aE[j][p]=0ull; aA[j][p]=0ull; }

    const float* pe = sE + 4*lane;
    const float* pa = sA + 4*lane;
    const float* pv = sV + 8*wp;
    #pragma unroll 2
    for (int kk = 0; kk < DD; kk++){
        ulonglong2 v01 = *(const ulonglong2*)(pv + kk*VP);
        ulonglong2 v23 = *(const ulonglong2*)(pv + kk*VP + 4);
        float4 we = *(const float4*)(pe + kk*DD);
        float4 wa = *(const float4*)(pa + kk*DD);
        float wef[4] = {we.x, we.y, we.z, we.w};
        float waf[4] = {wa.x, wa.y, wa.z, wa.w};
        #pragma unroll
        for (int j = 0; j < 4; j++){
            unsigned long long s = splat2(wef[j]);
            fma2(aE[j][0], v01.x, s); fma2(aE[j][1], v01.y, s);
            fma2(aE[j][2], v23.x, s); fma2(aE[j][3], v23.y, s);
        }
        #pragma unroll
        for (int j = 0; j < 4; j++){
            unsigned long long s = splat2(waf[j]);
            fma2(aA[j][0], v01.x, s); fma2(aA[j][1], v01.y, s);
            fma2(aA[j][2], v23.x, s); fma2(aA[j][3], v23.y, s);
        }
    }

    float4 eb4 = *(const float4*)(e_b + 4*lane);
    float4 ab4 = *(const float4*)(a_b + 4*lane);
    float ebf[4] = {eb4.x, eb4.y, eb4.z, eb4.w};
    float abf[4] = {ab4.x, ab4.y, ab4.z, ab4.w};
    #pragma unroll
    for (int p = 0; p < 4; p++){
        float2 he[4], ha[4];
        #pragma unroll
        for (int j = 0; j < 4; j++){ he[j] = unpk(aE[j][p]); ha[j] = unpk(aA[j][p]); }
        int t0 = tokbase + 8*wp + 2*p;
        float4 ev0, ev1, av0, av1;
        ev0.x = sigmoidf_(he[0].x + ebf[0]); ev0.y = sigmoidf_(he[1].x + ebf[1]);
        ev0.z = sigmoidf_(he[2].x + ebf[2]); ev0.w = sigmoidf_(he[3].x + ebf[3]);
        ev1.x = sigmoidf_(he[0].y + ebf[0]); ev1.y = sigmoidf_(he[1].y + ebf[1]);
        ev1.z = sigmoidf_(he[2].y + ebf[2]); ev1.w = sigmoidf_(he[3].y + ebf[3]);
        av0.x = tanhf(ha[0].x + abf[0]); av0.y = tanhf(ha[1].x + abf[1]);
        av0.z = tanhf(ha[2].x + abf[2]); av0.w = tanhf(ha[3].x + abf[3]);
        av1.x = tanhf(ha[0].y + abf[0]); av1.y = tanhf(ha[1].y + abf[1]);
        av1.z = tanhf(ha[2].y + abf[2]); av1.w = tanhf(ha[3].y + abf[3]);
        *(float4*)(g_e + (size_t)t0*DD + 4*lane)     = ev0;
        *(float4*)(g_e + (size_t)(t0+1)*DD + 4*lane) = ev1;
        *(float4*)(g_a + (size_t)t0*DD + 4*lane)     = av0;
        *(float4*)(g_a + (size_t)(t0+1)*DD + 4*lane) = av1;
    }
}

// ---------------- kernel 3: sequential scan over L ------------------------
// Grid (2 d-chunks, 64 batches). State Mv[50][64] per block in registers.
// w/e/a are recurrence-independent -> double-buffered prefetch.
__global__ void __launch_bounds__(256) scan_kernel(const float* __restrict__ Mv0,
                                                   float* __restrict__ out){
    const int b = blockIdx.y;
    const int chunk = blockIdx.x;
    const int tid = threadIdx.x;
    const int dl = tid & 63;
    const int d  = chunk*64 + dl;
    const int g  = tid >> 6;                 // 0..3, m = g + 4k
    const int nm = (g < 2) ? 13 : 12;
    __shared__ float s_red[4][64];

    float mv[13];
    #pragma unroll
    for (int k = 0; k < 13; k++){
        int m = g + 4*k;
        mv[k] = (k < nm) ? Mv0[m*DD + d] : 0.f;
    }
    float* outMv = out + NTOK;               // Mv block after p
    {   // state t=0 (init)
        float* o0 = outMv + (size_t)b*201*(MM*DD);
        #pragma unroll
        for (int k = 0; k < 13; k++) if (k < nm) o0[(g+4*k)*DD + d] = mv[k];
    }

    const float* wb = g_w + (size_t)b*LL*MM;
    const float* eb = g_e + (size_t)b*LL*DD;
    const float* ab = g_a + (size_t)b*LL*DD;

    float cw[13], ce, ca;
    #pragma unroll
    for (int k = 0; k < 13; k++) cw[k] = (k < nm) ? wb[g + 4*k] : 0.f;
    ce = eb[d]; ca = ab[d];

    for (int t = 0; t < LL; t++){
        // prefetch t+1 (independent of recurrence)
        float nw[13], ne = 0.f, na = 0.f;
        const bool more = (t + 1 < LL);
        if (more){
            #pragma unroll
            for (int k = 0; k < 13; k++) nw[k] = (k < nm) ? wb[(t+1)*MM + g + 4*k] : 0.f;
            ne = eb[(t+1)*DD + d]; na = ab[(t+1)*DD + d];
        }

        float* os = outMv + ((size_t)b*201 + t + 1)*(MM*DD);
        float rp0 = 0.f, rp1 = 0.f;
        #pragma unroll
        for (int k = 0; k < 13; k++){
            if (k < nm){
                float mo = mv[k];
                float wk = cw[k];
                if (k & 1) rp1 = fmaf(wk, mo, rp1); else rp0 = fmaf(wk, mo, rp0);
                float u = fmaf(wk, ca, mo);           // mo + w*a
                mv[k] = fmaf(-mo, wk*ce, u);          // - mo*w*e
                os[(g+4*k)*DD + d] = mv[k];
            }
        }
        s_red[g][dl] = rp0 + rp1;
        __syncthreads();
        if (g == 0){
            float rr = s_red[0][dl] + s_red[1][dl] + s_red[2][dl] + s_red[3][dl];
            g_read[((size_t)b*LL + t)*DD + d] = rr;
        }
        __syncthreads();
        if (more){
            #pragma unroll
            for (int k = 0; k < 13; k++) cw[k] = nw[k];
            ce = ne; ca = na;
        }
    }
}

// ---------------- kernel 4: f = tanh([read,k]@fW^T+b), p = sigmoid(f.pW+pb)
#define FP_TOK 64
#define FP_SMEM ((2*DD*DD + 2*DD*VP)*4)
__global__ void __launch_bounds__(256) fp_kernel(const int* __restrict__ q,
                                                 const float* __restrict__ k_emb,
                                                 const float* __restrict__ f_b,
                                                 const float* __restrict__ p_W,
                                                 const float* __restrict__ p_b,
                                                 float* __restrict__ outP){
    extern __shared__ float sm[];
    float* sW = sm;               // [256][128]
    float* sC = sm + 2*DD*DD;     // [256][VP]
    const int tid = threadIdx.x, lane = tid & 31, wp = tid >> 5;
    const int tokbase = blockIdx.x * FP_TOK;

    for (int i = tid; i < 2*DD*DD; i += 256) sW[i] = g_fWT[i];
    for (int jj = wp; jj < FP_TOK; jj += 8){
        int tok = tokbase + jj;
        const float* kr = k_emb + (size_t)q[tok]*DD;
        const float* rr = g_read + (size_t)tok*DD;
        #pragma unroll
        for (int ii = lane; ii < 2*DD; ii += 32){
            float v = (ii < DD) ? rr[ii] : kr[ii - DD];
            sC[ii*VP + jj] = v;
        }
    }
    __syncthreads();

    unsigned long long acc[4][4];
    #pragma unroll
    for (int j=0;j<4;j++)
        #pragma unroll
        for (int p=0;p<4;p++) acc[j][p]=0ull;

    const float* pw = sW + 4*lane;
    const float* pc = sC + 8*wp;
    #pragma unroll 2
    for (int kk = 0; kk < 2*DD; kk++){
        ulonglong2 v01 = *(const ulonglong2*)(pc + kk*VP);
        ulonglong2 v23 = *(const ulonglong2*)(pc + kk*VP + 4);
        float4 w4 = *(const float4*)(pw + kk*DD);
        float wf[4] = {w4.x, w4.y, w4.z, w4.w};
        #pragma unroll
        for (int j = 0; j < 4; j++){
            unsigned long long s = splat2(wf[j]);
            fma2(acc[j][0], v01.x, s); fma2(acc[j][1], v01.y, s);
            fma2(acc[j][2], v23.x, s); fma2(acc[j][3], v23.y, s);
        }
    }

    float4 fb4 = *(const float4*)(f_b + 4*lane);
    float4 pw4 = *(const float4*)(p_W + 4*lane);
    float fbf[4] = {fb4.x, fb4.y, fb4.z, fb4.w};
    float pwf[4] = {pw4.x, pw4.y, pw4.z, pw4.w};
    float pl[8];
    #pragma unroll
    for (int p = 0; p < 4; p++){
        float2 h[4];
        #pragma unroll
        for (int j = 0; j < 4; j++) h[j] = unpk(acc[j][p]);
        float s0 = 0.f, s1 = 0.f;
        #pragma unroll
        for (int j = 0; j < 4; j++){
            s0 = fmaf(tanhf(h[j].x + fbf[j]), pwf[j], s0);
            s1 = fmaf(tanhf(h[j].y + fbf[j]), pwf[j], s1);
        }
        pl[2*p] = s0; pl[2*p+1] = s1;
    }
    #pragma unroll
    for (int o = 16; o >= 1; o >>= 1)
        #pragma unroll
        for (int i = 0; i < 8; i++) pl[i] += __shfl_xor_sync(0xffffffffu, pl[i], o);
    const float pb = p_b[0];
    if (lane < 8){
        float myv = 0.f;
        #pragma unroll
        for (int i = 0; i < 8; i++) if (lane == i) myv = pl[i];
        outP[tokbase + 8*wp + lane] = sigmoidf_(myv + pb);
    }
}

// ---------------- launch ---------------------------------------------------
extern "C" void kernel_launch(void* const* d_in, const int* in_sizes, int n_in,
                              void* d_out, int out_size){
    (void)in_sizes; (void)n_in; (void)out_size;
    const int*   q     = (const int*)  d_in[0];
    const int*   r     = (const int*)  d_in[1];
    const float* k_emb = (const float*)d_in[2];
    const float* v_emb = (const float*)d_in[3];
    const float* Mk    = (const float*)d_in[4];
    const float* Mv0   = (const float*)d_in[5];
    const float* f_W   = (const float*)d_in[6];
    const float* f_b   = (const float*)d_in[7];
    const float* p_W   = (const float*)d_in[8];
    const float* p_b   = (const float*)d_in[9];
    const float* e_W   = (const float*)d_in[10];
    const float* e_b   = (const float*)d_in[11];
    const float* a_W   = (const float*)d_in[12];
    const float* a_b   = (const float*)d_in[13];
    float* out = (float*)d_out;

    cudaFuncSetAttribute(ea_kernel, cudaFuncAttributeMaxDynamicSharedMemorySize, EA_SMEM);
    cudaFuncSetAttribute(fp_kernel, cudaFuncAttributeMaxDynamicSharedMemorySize, FP_SMEM);

    tr_kernel<<<128, 256>>>(e_W, a_W, f_W);
    w_kernel<<<NTOK/W_TOK, 128>>>(q, k_emb, Mk);
    ea_kernel<<<NTOK/EA_TOK, 256, EA_SMEM>>>(q, r, v_emb, e_b, a_b);
    scan_kernel<<<dim3(2, BB), 256>>>(Mv0, out);
    fp_kernel<<<NTOK/FP_TOK, 256, FP_SMEM>>>(q, k_emb, f_b, p_W, p_b, out);
}

// round 3
// speedup vs baseline: 1.5398x; 1.5398x over previous
#include <cuda_runtime.h>
#include <cstdint>
#include <math.h>

#define BB 64
#define LL 200
#define DD 128
#define MM 50
#define NQ 10000
#define NTOK (BB*LL)

// ---------------- device scratch (no allocations allowed) ----------------
__device__ float g_w[NTOK*MM];        // softmax weights  [tok][50]
__device__ float g_e[NTOK*DD];        // erase gate       [tok][128]
__device__ float g_a[NTOK*DD];        // add gate         [tok][128]
__device__ float g_read[NTOK*DD];     // read vectors     [tok][128]
__device__ float g_eWT[DD*DD];        // e_W transposed [k][d]
__device__ float g_aWT[DD*DD];
__device__ float g_fWT[2*DD*DD];      // f_W transposed [k(256)][d(128)]

// ---------------- f32x2 helpers (sm_10x packed fp32 pipe) ----------------
__device__ __forceinline__ unsigned long long splat2(float x){
    unsigned long long r; asm("mov.b64 %0, {%1, %1};" : "=l"(r) : "f"(x)); return r;
}
__device__ __forceinline__ void fma2(unsigned long long &d, unsigned long long a, unsigned long long b){
    asm("fma.rn.f32x2 %0, %1, %2, %0;" : "+l"(d) : "l"(a), "l"(b));
}
__device__ __forceinline__ float2 unpk(unsigned long long v){
    float2 r; asm("mov.b64 {%0, %1}, %2;" : "=f"(r.x), "=f"(r.y) : "l"(v)); return r;
}
__device__ __forceinline__ float sigmoidf_(float x){ return 1.f/(1.f + __expf(-x)); }

// ---------------- kernel 0: one-time weight transposes --------------------
__global__ void tr_kernel(const float* __restrict__ eW, const float* __restrict__ aW,
                          const float* __restrict__ fW){
    int i = blockIdx.x*256 + threadIdx.x;
    if (i < DD*DD){
        int d = i >> 7, k = i & 127;
        g_eWT[k*DD + d] = eW[i];
        g_aWT[k*DD + d] = aW[i];
    }
    if (i < 2*DD*DD){
        int d = i >> 8, k = i & 255;      // fW is [128][256]
        g_fWT[k*DD + d] = fW[i];
    }
}

// ---------------- kernel 1: attention weights w = softmax(k @ Mk^T) -------
#define W_TOK 8
__global__ void __launch_bounds__(128) w_kernel(const int* __restrict__ q,
                                                const float* __restrict__ k_emb,
                                                const float* __restrict__ Mk){
    __shared__ float sMk[64*132];
    __shared__ float sK[W_TOK*DD];
    const int tid = threadIdx.x;
    const int tokbase = blockIdx.x * W_TOK;

    for (int i = tid; i < 64*132; i += 128) sMk[i] = 0.f;
    __syncthreads();
    for (int i = tid; i < MM*DD; i += 128) sMk[(i>>7)*132 + (i&127)] = Mk[i];
    #pragma unroll
    for (int jj = 0; jj < W_TOK; jj++)
        sK[jj*DD + tid] = k_emb[(size_t)q[tokbase+jj]*DD + tid];
    __syncthreads();

    const int j = tid >> 4, l16 = tid & 15;
    const float* kj = sK + j*DD;
    float acc[4] = {0.f,0.f,0.f,0.f};
    #pragma unroll 4
    for (int dd = 0; dd < DD; dd += 4){
        float4 kv = *(const float4*)(kj + dd);
        #pragma unroll
        for (int i = 0; i < 4; i++){
            int m = l16 + 16*i;
            float4 mk = *(const float4*)(sMk + m*132 + dd);
            acc[i] += kv.x*mk.x + kv.y*mk.y + kv.z*mk.z + kv.w*mk.w;
        }
    }
    #pragma unroll
    for (int i = 0; i < 4; i++) if (l16 + 16*i >= MM) acc[i] = -1e30f;
    float mx = fmaxf(fmaxf(acc[0],acc[1]), fmaxf(acc[2],acc[3]));
    #pragma unroll
    for (int o = 8; o >= 1; o >>= 1) mx = fmaxf(mx, __shfl_xor_sync(0xffffffffu, mx, o));
    float ex[4], s = 0.f;
    #pragma unroll
    for (int i = 0; i < 4; i++){ ex[i] = __expf(acc[i] - mx); s += ex[i]; }
    #pragma unroll
    for (int o = 8; o >= 1; o >>= 1) s += __shfl_xor_sync(0xffffffffu, s, o);
    float inv = 1.f / s;
    #pragma unroll
    for (int i = 0; i < 4; i++){
        int m = l16 + 16*i;
        if (m < MM) g_w[(size_t)(tokbase + j)*MM + m] = ex[i]*inv;
    }
}

// ---------------- kernel 2: e = sigmoid(v@eW^T+b), a = tanh(v@aW^T+b) -----
#define EA_TOK 64
#define VP 68
#define EA_SMEM ((2*DD*DD + DD*VP)*4)
__global__ void __launch_bounds__(256) ea_kernel(const int* __restrict__ q,
                                                 const int* __restrict__ r,
                                                 const float* __restrict__ v_emb,
                                                 const float* __restrict__ e_b,
                                                 const float* __restrict__ a_b){
    extern __shared__ float sm[];
    float* sE = sm;
    float* sA = sm + DD*DD;
    float* sV = sm + 2*DD*DD;
    const int tid = threadIdx.x, lane = tid & 31, wp = tid >> 5;
    const int tokbase = blockIdx.x * EA_TOK;

    for (int i = tid; i < DD*DD; i += 256){ sE[i] = g_eWT[i]; sA[i] = g_aWT[i]; }
    for (int jj = wp; jj < EA_TOK; jj += 8){
        int tok = tokbase + jj;
        int x = q[tok] + NQ * r[tok];
        const float* vr = v_emb + (size_t)x * DD;
        #pragma unroll
        for (int dd = lane; dd < DD; dd += 32) sV[dd*VP + jj] = vr[dd];
    }
    __syncthreads();

    unsigned long long aE[4][4], aA[4][4];
    #pragma unroll
    for (int j=0;j<4;j++)
        #pragma unroll
        for (int p=0;p<4;p++){ aE[j][p]=0ull; aA[j][p]=0ull; }

    const float* pe = sE + 4*lane;
    const float* pa = sA + 4*lane;
    const float* pv = sV + 8*wp;
    #pragma unroll 2
    for (int kk = 0; kk < DD; kk++){
        ulonglong2 v01 = *(const ulonglong2*)(pv + kk*VP);
        ulonglong2 v23 = *(const ulonglong2*)(pv + kk*VP + 4);
        float4 we = *(const float4*)(pe + kk*DD);
        float4 wa = *(const float4*)(pa + kk*DD);
        float wef[4] = {we.x, we.y, we.z, we.w};
        float waf[4] = {wa.x, wa.y, wa.z, wa.w};
        #pragma unroll
        for (int j = 0; j < 4; j++){
            unsigned long long s = splat2(wef[j]);
            fma2(aE[j][0], v01.x, s); fma2(aE[j][1], v01.y, s);
            fma2(aE[j][2], v23.x, s); fma2(aE[j][3], v23.y, s);
        }
        #pragma unroll
        for (int j = 0; j < 4; j++){
            unsigned long long s = splat2(waf[j]);
            fma2(aA[j][0], v01.x, s); fma2(aA[j][1], v01.y, s);
            fma2(aA[j][2], v23.x, s); fma2(aA[j][3], v23.y, s);
        }
    }

    float4 eb4 = *(const float4*)(e_b + 4*lane);
    float4 ab4 = *(const float4*)(a_b + 4*lane);
    float ebf[4] = {eb4.x, eb4.y, eb4.z, eb4.w};
    float abf[4] = {ab4.x, ab4.y, ab4.z, ab4.w};
    #pragma unroll
    for (int p = 0; p < 4; p++){
        float2 he[4], ha[4];
        #pragma unroll
        for (int j = 0; j < 4; j++){ he[j] = unpk(aE[j][p]); ha[j] = unpk(aA[j][p]); }
        int t0 = tokbase + 8*wp + 2*p;
        float4 ev0, ev1, av0, av1;
        ev0.x = sigmoidf_(he[0].x + ebf[0]); ev0.y = sigmoidf_(he[1].x + ebf[1]);
        ev0.z = sigmoidf_(he[2].x + ebf[2]); ev0.w = sigmoidf_(he[3].x + ebf[3]);
        ev1.x = sigmoidf_(he[0].y + ebf[0]); ev1.y = sigmoidf_(he[1].y + ebf[1]);
        ev1.z = sigmoidf_(he[2].y + ebf[2]); ev1.w = sigmoidf_(he[3].y + ebf[3]);
        av0.x = tanhf(ha[0].x + abf[0]); av0.y = tanhf(ha[1].x + abf[1]);
        av0.z = tanhf(ha[2].x + abf[2]); av0.w = tanhf(ha[3].x + abf[3]);
        av1.x = tanhf(ha[0].y + abf[0]); av1.y = tanhf(ha[1].y + abf[1]);
        av1.z = tanhf(ha[2].y + abf[2]); av1.w = tanhf(ha[3].y + abf[3]);
        *(float4*)(g_e + (size_t)t0*DD + 4*lane)     = ev0;
        *(float4*)(g_e + (size_t)(t0+1)*DD + 4*lane) = ev1;
        *(float4*)(g_a + (size_t)t0*DD + 4*lane)     = av0;
        *(float4*)(g_a + (size_t)(t0+1)*DD + 4*lane) = av1;
    }
}

// ---------------- kernel 3: sequential scan over L (BARRIER-FREE) ---------
// Grid (2 d-chunks, 64 batches), 256 threads. Lane map: lane = mg*8 + d8.
// Warp covers 8 consecutive d, all 4 m-groups -> read-reduction via shfl.xor.
// Mv output written with streaming stores (keeps w/e/a hot in L2).
__global__ void __launch_bounds__(256) scan_kernel(const float* __restrict__ Mv0,
                                                   float* __restrict__ out){
    const int b = blockIdx.y;
    const int chunk = blockIdx.x;
    const int tid = threadIdx.x;
    const int lane = tid & 31;
    const int wp = tid >> 5;               // warp 0..7
    const int mg = lane >> 3;              // m-group 0..3
    const int d8 = lane & 7;
    const int d  = chunk*64 + wp*8 + d8;   // warp covers 8 consecutive d
    const int nm = (mg < 2) ? 13 : 12;     // m = mg + 4*k

    float mv[13];
    #pragma unroll
    for (int k = 0; k < 13; k++){
        int m = mg + 4*k;
        mv[k] = (k < nm) ? Mv0[m*DD + d] : 0.f;
    }
    float* outMv = out + NTOK;             // Mv block after p
    {   // state t=0 (init)
        float* o0 = outMv + (size_t)b*201*(MM*DD);
        #pragma unroll
        for (int k = 0; k < 13; k++) if (k < nm) __stcs(o0 + (mg+4*k)*DD + d, mv[k]);
    }

    const float* wb = g_w + (size_t)b*LL*MM;
    const float* eb = g_e + (size_t)b*LL*DD;
    const float* ab = g_a + (size_t)b*LL*DD;

    float cw[13], ce, ca;
    #pragma unroll
    for (int k = 0; k < 13; k++) cw[k] = (k < nm) ? wb[mg + 4*k] : 0.f;
    ce = eb[d]; ca = ab[d];

    for (int t = 0; t < LL; t++){
        // prefetch t+1 (independent of recurrence)
        float nw[13], ne = 0.f, na = 0.f;
        const bool more = (t + 1 < LL);
        if (more){
            #pragma unroll
            for (int k = 0; k < 13; k++) nw[k] = (k < nm) ? wb[(t+1)*MM + mg + 4*k] : 0.f;
            ne = eb[(t+1)*DD + d]; na = ab[(t+1)*DD + d];
        }

        float* os = outMv + ((size_t)b*201 + t + 1)*(MM*DD);
        float rp0 = 0.f, rp1 = 0.f;
        // update + store first (fire-and-forget stores into LSU queue)
        #pragma unroll
        for (int k = 0; k < 13; k++){
            if (k < nm){
                float mo = mv[k];
                float wk = cw[k];
                float u = fmaf(wk, ca, mo);           // mo + w*a
                mv[k] = fmaf(-mo, wk*ce, u);          // - mo*w*e
                __stcs(os + (mg+4*k)*DD + d, mv[k]);
                if (k & 1) rp1 = fmaf(wk, mo, rp1); else rp0 = fmaf(wk, mo, rp0);
            }
        }
        // in-warp reduction over the 4 m-groups (same d lives at lane^8, lane^16)
        float rr = rp0 + rp1;
        rr += __shfl_xor_sync(0xffffffffu, rr, 8);
        rr += __shfl_xor_sync(0xffffffffu, rr, 16);
        if (mg == 0)
            g_read[((size_t)b*LL + t)*DD + d] = rr;

        if (more){
            #pragma unroll
            for (int k = 0; k < 13; k++) cw[k] = nw[k];
            ce = ne; ca = na;
        }
    }
}

// ---------------- kernel 4: f = tanh([read,k]@fW^T+b), p = sigmoid(f.pW+pb)
#define FP_TOK 64
#define FP_SMEM ((2*DD*DD + 2*DD*VP)*4)
__global__ void __launch_bounds__(256) fp_kernel(const int* __restrict__ q,
                                                 const float* __restrict__ k_emb,
                                                 const float* __restrict__ f_b,
                                                 const float* __restrict__ p_W,
                                                 const float* __restrict__ p_b,
                                                 float* __restrict__ outP){
    extern __shared__ float sm[];
    float* sW = sm;               // [256][128]
    float* sC = sm + 2*DD*DD;     // [256][VP]
    const int tid = threadIdx.x, lane = tid & 31, wp = tid >> 5;
    const int tokbase = blockIdx.x * FP_TOK;

    for (int i = tid; i < 2*DD*DD; i += 256) sW[i] = g_fWT[i];
    for (int jj = wp; jj < FP_TOK; jj += 8){
        int tok = tokbase + jj;
        const float* kr = k_emb + (size_t)q[tok]*DD;
        const float* rr = g_read + (size_t)tok*DD;
        #pragma unroll
        for (int ii = lane; ii < 2*DD; ii += 32){
            float v = (ii < DD) ? rr[ii] : kr[ii - DD];
            sC[ii*VP + jj] = v;
        }
    }
    __syncthreads();

    unsigned long long acc[4][4];
    #pragma unroll
    for (int j=0;j<4;j++)
        #pragma unroll
        for (int p=0;p<4;p++) acc[j][p]=0ull;

    const float* pw = sW + 4*lane;
    const float* pc = sC + 8*wp;
    #pragma unroll 2
    for (int kk = 0; kk < 2*DD; kk++){
        ulonglong2 v01 = *(const ulonglong2*)(pc + kk*VP);
        ulonglong2 v23 = *(const ulonglong2*)(pc + kk*VP + 4);
        float4 w4 = *(const float4*)(pw + kk*DD);
        float wf[4] = {w4.x, w4.y, w4.z, w4.w};
        #pragma unroll
        for (int j = 0; j < 4; j++){
            unsigned long long s = splat2(wf[j]);
            fma2(acc[j][0], v01.x, s); fma2(acc[j][1], v01.y, s);
            fma2(acc[j][2], v23.x, s); fma2(acc[j][3], v23.y, s);
        }
    }

    float4 fb4 = *(const float4*)(f_b + 4*lane);
    float4 pw4 = *(const float4*)(p_W + 4*lane);
    float fbf[4] = {fb4.x, fb4.y, fb4.z, fb4.w};
    float pwf[4] = {pw4.x, pw4.y, pw4.z, pw4.w};
    float pl[8];
    #pragma unroll
    for (int p = 0; p < 4; p++){
        float2 h[4];
        #pragma unroll
        for (int j = 0; j < 4; j++) h[j] = unpk(acc[j][p]);
        float s0 = 0.f, s1 = 0.f;
        #pragma unroll
        for (int j = 0; j < 4; j++){
            s0 = fmaf(tanhf(h[j].x + fbf[j]), pwf[j], s0);
            s1 = fmaf(tanhf(h[j].y + fbf[j]), pwf[j], s1);
        }
        pl[2*p] = s0; pl[2*p+1] = s1;
    }
    #pragma unroll
    for (int o = 16; o >= 1; o >>= 1)
        #pragma unroll
        for (int i = 0; i < 8; i++) pl[i] += __shfl_xor_sync(0xffffffffu, pl[i], o);
    const float pb = p_b[0];
    if (lane < 8){
        float myv = 0.f;
        #pragma unroll
        for (int i = 0; i < 8; i++) if (lane == i) myv = pl[i];
        outP[tokbase + 8*wp + lane] = sigmoidf_(myv + pb);
    }
}

// ---------------- launch ---------------------------------------------------
extern "C" void kernel_launch(void* const* d_in, const int* in_sizes, int n_in,
                              void* d_out, int out_size){
    (void)in_sizes; (void)n_in; (void)out_size;
    const int*   q     = (const int*)  d_in[0];
    const int*   r     = (const int*)  d_in[1];
    const float* k_emb = (const float*)d_in[2];
    const float* v_emb = (const float*)d_in[3];
    const float* Mk    = (const float*)d_in[4];
    const float* Mv0   = (const float*)d_in[5];
    const float* f_W   = (const float*)d_in[6];
    const float* f_b   = (const float*)d_in[7];
    const float* p_W   = (const float*)d_in[8];
    const float* p_b   = (const float*)d_in[9];
    const float* e_W   = (const float*)d_in[10];
    const float* e_b   = (const float*)d_in[11];
    const float* a_W   = (const float*)d_in[12];
    const float* a_b   = (const float*)d_in[13];
    float* out = (float*)d_out;

    cudaFuncSetAttribute(ea_kernel, cudaFuncAttributeMaxDynamicSharedMemorySize, EA_SMEM);
    cudaFuncSetAttribute(fp_kernel, cudaFuncAttributeMaxDynamicSharedMemorySize, FP_SMEM);

    tr_kernel<<<128, 256>>>(e_W, a_W, f_W);
    w_kernel<<<NTOK/W_TOK, 128>>>(q, k_emb, Mk);
    ea_kernel<<<NTOK/EA_TOK, 256, EA_SMEM>>>(q, r, v_emb, e_b, a_b);
    scan_kernel<<<dim3(2, BB), 256>>>(Mv0, out);
    fp_kernel<<<NTOK/FP_TOK, 256, FP_SMEM>>>(q, k_emb, f_b, p_W, p_b, out);
}